// round 5
// baseline (speedup 1.0000x reference)
#include <cuda_runtime.h>
#include <cuda_bf16.h>
#include <math.h>

#define H 512
#define W 512
#define NPIX (H * W)
#define NWORDS 16            // 512 rows / 32 bits
#define NBLK 256             // k_fused blocks (2 rows each)

// Scratch (allocation-free rule: __device__ globals)
// d_pack[q*512 + c] = (wordA, wordB): bit j of wordA = surface-of-pred at
// (row = q*32 + j, col = c); wordB likewise for gt. Coalesced in c.
__device__ uint2 d_pack[NWORDS * W];
__device__ float d_blkNum[NBLK];
__device__ float d_blkDen[NBLK];
__device__ unsigned int d_cnt;   // zero-init; atomicInc wraps -> self-resetting

// ---------------------------------------------------------------------------
// Kernel 1: binarize + erode + surface + column bit-pack, ballot-native.
// Block (32,32) handles a 32x32 tile. One float LDG per feature per thread;
// erosion done bitwise on row words; 32x32 bit transpose via shared words.
// ---------------------------------------------------------------------------
__global__ void __launch_bounds__(1024) k_pack(const float* __restrict__ pred,
                                               const float* __restrict__ gt) {
    __shared__ unsigned rowA[34], rowB[34];   // row words with +-1 halo
    __shared__ unsigned surA[32], surB[32];   // surface row words

    const int tx = threadIdx.x;   // lane = column within tile
    const int ty = threadIdx.y;   // warp = row within tile
    const int c0 = blockIdx.x * 32;
    const int r0 = blockIdx.y * 32;
    const int c = c0 + tx;
    const int r = r0 + ty;

    // Own row words via ballot (1 LDG per feature per thread)
    const float* prow = pred + r * W;
    const float* grow = gt + r * W;
    unsigned wA = __ballot_sync(0xFFFFFFFFu, prow[c] != 0.0f);
    unsigned wB = __ballot_sync(0xFFFFFFFFu, grow[c] != 0.0f);
    if (tx == 0) { rowA[ty + 1] = wA; rowB[ty + 1] = wB; }

    // Halo rows (warp 0: row r0-1, warp 1: row r0+32)
    if (ty == 0) {
        bool a = (r0 > 0) && (pred[(r0 - 1) * W + c] != 0.0f);
        bool b = (r0 > 0) && (gt[(r0 - 1) * W + c] != 0.0f);
        unsigned ha = __ballot_sync(0xFFFFFFFFu, a);
        unsigned hb = __ballot_sync(0xFFFFFFFFu, b);
        if (tx == 0) { rowA[0] = ha; rowB[0] = hb; }
    } else if (ty == 1) {
        bool a = (r0 + 32 < H) && (pred[(r0 + 32) * W + c] != 0.0f);
        bool b = (r0 + 32 < H) && (gt[(r0 + 32) * W + c] != 0.0f);
        unsigned ha = __ballot_sync(0xFFFFFFFFu, a);
        unsigned hb = __ballot_sync(0xFFFFFFFFu, b);
        if (tx == 0) { rowA[33] = ha; rowB[33] = hb; }
    }

    // Halo columns for this row (lane 0: c0-1, lane 1: c0+32)
    bool hv = false;
    if (tx == 0 && c0 > 0)          hv = prow[c0 - 1] != 0.0f;
    if (tx == 1 && c0 + 32 < W)     hv = prow[c0 + 32] != 0.0f;
    unsigned hm = __ballot_sync(0xFFFFFFFFu, hv);
    bool hlA = hm & 1u, hrA = (hm >> 1) & 1u;
    hv = false;
    if (tx == 0 && c0 > 0)          hv = grow[c0 - 1] != 0.0f;
    if (tx == 1 && c0 + 32 < W)     hv = grow[c0 + 32] != 0.0f;
    hm = __ballot_sync(0xFFFFFFFFu, hv);
    bool hlB = hm & 1u, hrB = (hm >> 1) & 1u;

    __syncthreads();

    // Bitwise erosion -> surface words (one warp per row; lanes redundant)
    if (tx == 0) {
        unsigned upA = rowA[ty], dnA = rowA[ty + 2];
        unsigned upB = rowB[ty], dnB = rowB[ty + 2];
        unsigned lmA = (wA << 1) | (hlA ? 1u : 0u);
        unsigned rmA = (wA >> 1) | (hrA ? 0x80000000u : 0u);
        unsigned lmB = (wB << 1) | (hlB ? 1u : 0u);
        unsigned rmB = (wB >> 1) | (hrB ? 0x80000000u : 0u);
        surA[ty] = wA & ~(upA & dnA & lmA & rmA);
        surB[ty] = wB & ~(upB & dnB & lmB & rmB);
    }
    __syncthreads();

    // 32x32 bit transpose: warp ty builds column word for column c0+ty.
    // Each LDS is a within-warp broadcast (same address) -> conflict-free.
    unsigned colA = 0, colB = 0;
    #pragma unroll
    for (int j = 0; j < 32; ++j) {
        colA |= ((surA[j] >> ty) & 1u) << j;
        colB |= ((surB[j] >> ty) & 1u) << j;
    }
    if (tx == 0) {
        d_pack[blockIdx.y * W + c0 + ty] = make_uint2(colA, colB);
    }
}

// ---------------------------------------------------------------------------
// Exact vertical squared distance from (row q*32+bit, col c) to nearest set
// bit in the packed column. col = &d_pack[c], stride W per word.
// ---------------------------------------------------------------------------
__device__ __forceinline__ float vdist2_bits(unsigned wcur, int q, int bit,
                                             const uint2* __restrict__ col,
                                             bool compB) {
    int du;
    unsigned upm = wcur & (0xFFFFFFFFu >> (31 - bit));
    if (upm) {
        du = bit - (31 - __clz(upm));
    } else {
        du = 1 << 20;
        for (int s = 1; s <= q; ++s) {
            uint2 v = col[(q - s) * W];
            unsigned x = compB ? v.y : v.x;
            if (x) { du = bit + s * 32 - (31 - __clz(x)); break; }
        }
    }
    int dd;
    unsigned dnm = wcur >> bit;
    if (dnm) {
        dd = __ffs(dnm) - 1;
    } else {
        dd = 1 << 20;
        for (int s = 1; q + s < NWORDS; ++s) {
            uint2 v = col[(q + s) * W];
            unsigned x = compB ? v.y : v.x;
            if (x) { dd = (32 - bit) + (s - 1) * 32 + (__ffs(x) - 1); break; }
        }
    }
    int dmin = min(du, dd);
    if (dmin >= (1 << 20)) return 1e12f;
    float f = (float)dmin;
    return f * f;
}

// Exact row min-plus: batched head (d<=3) + early-exit tail. g2 >= 0 makes
// the break at d*d >= best exact; extra candidates can only be >= the min.
__device__ __forceinline__ float edt_scan(const float* __restrict__ g2, int c) {
    float best = g2[c];
    #pragma unroll
    for (int d = 1; d <= 3; ++d) {
        float dd = (float)(d * d);
        if (c - d >= 0) best = fminf(best, g2[c - d] + dd);
        if (c + d <  W) best = fminf(best, g2[c + d] + dd);
    }
    for (int d = 4; d < W; ++d) {
        float dd = (float)(d * d);
        if (dd >= best) break;
        if (c - d >= 0) best = fminf(best, g2[c - d] + dd);
        if (c + d <  W) best = fminf(best, g2[c + d] + dd);
    }
    return sqrtf(best);
}

// ---------------------------------------------------------------------------
// Fused kernel: one block per TWO rows (r0 = 2*bid, r0+1). Both rows live in
// the same packed word (r0 even), so one uint2 load serves both.
// ---------------------------------------------------------------------------
__global__ void __launch_bounds__(W) k_fused(float* __restrict__ out) {
    __shared__ float sA0[W], sA1[W], sB0[W], sB1[W];
    __shared__ float wNum[16], wDen[16];
    __shared__ bool  isLast;

    const int r0 = blockIdx.x * 2;
    const int c = threadIdx.x;
    const int q = r0 >> 5;
    const int b0 = r0 & 31;       // even, <= 30
    const int b1 = b0 + 1;
    const int lane = c & 31;
    const int wid = c >> 5;

    const uint2 pw = d_pack[q * W + c];
    const bool onS0  = (pw.x >> b0) & 1u;
    const bool onS1  = (pw.x >> b1) & 1u;
    const bool onSp0 = (pw.y >> b0) & 1u;
    const bool onSp1 = (pw.y >> b1) & 1u;

    const uint2* colp = &d_pack[c];
    sA0[c] = vdist2_bits(pw.x, q, b0, colp, false);
    sA1[c] = vdist2_bits(pw.x, q, b1, colp, false);
    sB0[c] = vdist2_bits(pw.y, q, b0, colp, true);
    sB1[c] = vdist2_bits(pw.y, q, b1, colp, true);
    __syncthreads();

    float num = 0.0f;
    float den = 0.0f;
    if (onSp0) { num += edt_scan(sA0, c); den += 1.0f; }  // dta on S' row0
    if (onSp1) { num += edt_scan(sA1, c); den += 1.0f; }  // dta on S' row1
    if (onS0)  { num += edt_scan(sB0, c); den += 1.0f; }  // dtb on S  row0
    if (onS1)  { num += edt_scan(sB1, c); den += 1.0f; }  // dtb on S  row1

    // warp shuffle reduction (deterministic)
    #pragma unroll
    for (int off = 16; off > 0; off >>= 1) {
        num += __shfl_down_sync(0xFFFFFFFFu, num, off);
        den += __shfl_down_sync(0xFFFFFFFFu, den, off);
    }
    if (lane == 0) { wNum[wid] = num; wDen[wid] = den; }
    __syncthreads();

    if (wid == 0) {
        float n = (lane < 16) ? wNum[lane] : 0.0f;
        float d = (lane < 16) ? wDen[lane] : 0.0f;
        #pragma unroll
        for (int off = 8; off > 0; off >>= 1) {
            n += __shfl_down_sync(0xFFFFFFFFu, n, off);
            d += __shfl_down_sync(0xFFFFFFFFu, d, off);
        }
        if (lane == 0) {
            d_blkNum[blockIdx.x] = n;
            d_blkDen[blockIdx.x] = d;
            __threadfence();
            unsigned int old = atomicInc(&d_cnt, NBLK - 1);  // wraps -> reset
            isLast = (old == NBLK - 1);
        }
    }
    __syncthreads();

    // last block folds the 256 block partials
    if (isLast) {
        float n = (c < NBLK) ? d_blkNum[c] : 0.0f;
        float d = (c < NBLK) ? d_blkDen[c] : 0.0f;
        #pragma unroll
        for (int off = 16; off > 0; off >>= 1) {
            n += __shfl_down_sync(0xFFFFFFFFu, n, off);
            d += __shfl_down_sync(0xFFFFFFFFu, d, off);
        }
        if (lane == 0) { wNum[wid] = n; wDen[wid] = d; }
        __syncthreads();
        if (wid == 0) {
            float nn = (lane < 16) ? wNum[lane] : 0.0f;
            float dd = (lane < 16) ? wDen[lane] : 0.0f;
            #pragma unroll
            for (int off = 8; off > 0; off >>= 1) {
                nn += __shfl_down_sync(0xFFFFFFFFu, nn, off);
                dd += __shfl_down_sync(0xFFFFFFFFu, dd, off);
            }
            if (lane == 0) out[0] = nn / dd;
        }
    }
}

extern "C" void kernel_launch(void* const* d_in, const int* in_sizes, int n_in,
                              void* d_out, int out_size) {
    const float* pred = (const float*)d_in[0];
    const float* gt   = (const float*)d_in[1];
    float* out = (float*)d_out;

    dim3 blk(32, 32);
    dim3 grd(W / 32, H / 32);
    k_pack<<<grd, blk>>>(pred, gt);
    k_fused<<<NBLK, W>>>(out);
}

// round 6
// speedup vs baseline: 1.1373x; 1.1373x over previous
#include <cuda_runtime.h>
#include <cuda_bf16.h>
#include <math.h>

#define H 512
#define W 512
#define NPIX (H * W)
#define NWORDS 16            // 512 rows / 32 bits

// Scratch (allocation-free rule: __device__ globals)
// d_packA[q*512 + c]: bit j = surface-of-pred at (row q*32+j, col c).
// d_packB likewise for gt. Coalesced in c.
__device__ unsigned d_packA[NWORDS * W];
__device__ unsigned d_packB[NWORDS * W];
__device__ float d_rowNum[H];
__device__ float d_rowDen[H];
__device__ unsigned int d_cnt;   // zero-init; atomicInc wraps -> self-resetting

// ---------------------------------------------------------------------------
// 32x32 bit-matrix transpose within one warp (butterfly, 5 steps).
// In: lane l holds row-word l (bit c = M[l][c]). Out: lane l holds bit j=M[j][l].
// ---------------------------------------------------------------------------
__device__ __forceinline__ unsigned bit_transpose32(unsigned x, int lane) {
    #pragma unroll
    for (int i = 0; i < 5; ++i) {
        const int s = 16 >> i;
        const unsigned m = (i == 0) ? 0xFFFF0000u :
                           (i == 1) ? 0xFF00FF00u :
                           (i == 2) ? 0xF0F0F0F0u :
                           (i == 3) ? 0xCCCCCCCCu : 0xAAAAAAAAu;
        unsigned y = __shfl_xor_sync(0xFFFFFFFFu, x, s);
        x = (lane & s) ? ((x & m) | ((y >> s) & ~m))
                       : ((x & ~m) | ((y << s) & m));
    }
    return x;
}

// ---------------------------------------------------------------------------
// Kernel 1: binarize + erode + surface + column bit-pack.
// Block (32,32) = one 32x32 tile; coalesced loads + ballot row-words,
// bitwise erosion, then warp0/warp1 do in-register bit transposes.
// ---------------------------------------------------------------------------
__global__ void __launch_bounds__(1024) k_pack(const float* __restrict__ pred,
                                               const float* __restrict__ gt) {
    __shared__ unsigned rowA[34], rowB[34];   // row words with +-1 halo
    __shared__ unsigned surA[32], surB[32];   // surface row words

    const int tx = threadIdx.x;   // lane = column within tile
    const int ty = threadIdx.y;   // warp = row within tile
    const int c0 = blockIdx.x * 32;
    const int r0 = blockIdx.y * 32;
    const int c = c0 + tx;
    const int r = r0 + ty;

    const float* prow = pred + r * W;
    const float* grow = gt + r * W;
    unsigned wA = __ballot_sync(0xFFFFFFFFu, prow[c] != 0.0f);
    unsigned wB = __ballot_sync(0xFFFFFFFFu, grow[c] != 0.0f);
    if (tx == 0) { rowA[ty + 1] = wA; rowB[ty + 1] = wB; }

    // Halo rows
    if (ty == 0) {
        bool a = (r0 > 0) && (pred[(r0 - 1) * W + c] != 0.0f);
        bool b = (r0 > 0) && (gt[(r0 - 1) * W + c] != 0.0f);
        unsigned ha = __ballot_sync(0xFFFFFFFFu, a);
        unsigned hb = __ballot_sync(0xFFFFFFFFu, b);
        if (tx == 0) { rowA[0] = ha; rowB[0] = hb; }
    } else if (ty == 1) {
        bool a = (r0 + 32 < H) && (pred[(r0 + 32) * W + c] != 0.0f);
        bool b = (r0 + 32 < H) && (gt[(r0 + 32) * W + c] != 0.0f);
        unsigned ha = __ballot_sync(0xFFFFFFFFu, a);
        unsigned hb = __ballot_sync(0xFFFFFFFFu, b);
        if (tx == 0) { rowA[33] = ha; rowB[33] = hb; }
    }

    // Halo columns for this row (lane 0: c0-1, lane 1: c0+32)
    bool hv = false;
    if (tx == 0 && c0 > 0)      hv = prow[c0 - 1] != 0.0f;
    if (tx == 1 && c0 + 32 < W) hv = prow[c0 + 32] != 0.0f;
    unsigned hm = __ballot_sync(0xFFFFFFFFu, hv);
    const bool hlA = hm & 1u, hrA = (hm >> 1) & 1u;
    hv = false;
    if (tx == 0 && c0 > 0)      hv = grow[c0 - 1] != 0.0f;
    if (tx == 1 && c0 + 32 < W) hv = grow[c0 + 32] != 0.0f;
    hm = __ballot_sync(0xFFFFFFFFu, hv);
    const bool hlB = hm & 1u, hrB = (hm >> 1) & 1u;

    __syncthreads();

    // Bitwise erosion -> surface row words
    if (tx == 0) {
        unsigned upA = rowA[ty], dnA = rowA[ty + 2];
        unsigned upB = rowB[ty], dnB = rowB[ty + 2];
        unsigned lmA = (wA << 1) | (hlA ? 1u : 0u);
        unsigned rmA = (wA >> 1) | (hrA ? 0x80000000u : 0u);
        unsigned lmB = (wB << 1) | (hlB ? 1u : 0u);
        unsigned rmB = (wB >> 1) | (hrB ? 0x80000000u : 0u);
        surA[ty] = wA & ~(upA & dnA & lmA & rmA);
        surB[ty] = wB & ~(upB & dnB & lmB & rmB);
    }
    __syncthreads();

    // In-register transposes: warp 0 -> feature A, warp 1 -> feature B.
    if (ty == 0) {
        unsigned x = bit_transpose32(surA[tx], tx);
        d_packA[blockIdx.y * W + c0 + tx] = x;
    } else if (ty == 1) {
        unsigned x = bit_transpose32(surB[tx], tx);
        d_packB[blockIdx.y * W + c0 + tx] = x;
    }
}

// ---------------------------------------------------------------------------
// Exact vertical squared distance from (row q*32+bit, col c) to nearest set
// bit in the packed column. col = &pack[c], stride W per word.
// ---------------------------------------------------------------------------
__device__ __forceinline__ float vdist2_bits(unsigned wcur, int q, int bit,
                                             const unsigned* __restrict__ col) {
    int du;
    unsigned upm = wcur & (0xFFFFFFFFu >> (31 - bit));
    if (upm) {
        du = bit - (31 - __clz(upm));
    } else {
        du = 1 << 20;
        for (int s = 1; s <= q; ++s) {
            unsigned x = col[(q - s) * W];
            if (x) { du = bit + s * 32 - (31 - __clz(x)); break; }
        }
    }
    int dd;
    unsigned dnm = wcur >> bit;
    if (dnm) {
        dd = __ffs(dnm) - 1;
    } else {
        dd = 1 << 20;
        for (int s = 1; q + s < NWORDS; ++s) {
            unsigned x = col[(q + s) * W];
            if (x) { dd = (32 - bit) + (s - 1) * 32 + (__ffs(x) - 1); break; }
        }
    }
    int dmin = min(du, dd);
    if (dmin >= (1 << 20)) return 1e12f;
    float f = (float)dmin;
    return f * f;
}

// ---------------------------------------------------------------------------
// Fused kernel: one block per row (grid 512 for occupancy/latency hiding).
// ---------------------------------------------------------------------------
__global__ void __launch_bounds__(W) k_fused(float* __restrict__ out) {
    __shared__ float sA[W];     // g2 for feature S   (-> dta)
    __shared__ float sB[W];     // g2 for feature S'  (-> dtb)
    __shared__ float wNum[16];
    __shared__ float wDen[16];
    __shared__ bool  isLast;

    const int r = blockIdx.x;
    const int c = threadIdx.x;
    const int q = r >> 5;
    const int bit = r & 31;
    const int lane = c & 31;
    const int wid = c >> 5;

    const unsigned pwA = d_packA[q * W + c];
    const unsigned pwB = d_packB[q * W + c];
    const bool onS  = (pwA >> bit) & 1u;
    const bool onSp = (pwB >> bit) & 1u;

    sA[c] = vdist2_bits(pwA, q, bit, &d_packA[c]);
    sB[c] = vdist2_bits(pwB, q, bit, &d_packB[c]);
    __syncthreads();

    // exact row min-plus: batched head (d<=3) + early-exit tail
    float num = 0.0f;
    float den = 0.0f;

    if (onSp) {   // dta sampled on S'
        float best = sA[c];
        #pragma unroll
        for (int d = 1; d <= 3; ++d) {
            float dd = (float)(d * d);
            if (c - d >= 0) best = fminf(best, sA[c - d] + dd);
            if (c + d <  W) best = fminf(best, sA[c + d] + dd);
        }
        for (int d = 4; d < W; ++d) {
            float dd = (float)(d * d);
            if (dd >= best) break;
            if (c - d >= 0) best = fminf(best, sA[c - d] + dd);
            if (c + d <  W) best = fminf(best, sA[c + d] + dd);
        }
        num += sqrtf(best);
        den += 1.0f;
    }
    if (onS) {    // dtb sampled on S
        float best = sB[c];
        #pragma unroll
        for (int d = 1; d <= 3; ++d) {
            float dd = (float)(d * d);
            if (c - d >= 0) best = fminf(best, sB[c - d] + dd);
            if (c + d <  W) best = fminf(best, sB[c + d] + dd);
        }
        for (int d = 4; d < W; ++d) {
            float dd = (float)(d * d);
            if (dd >= best) break;
            if (c - d >= 0) best = fminf(best, sB[c - d] + dd);
            if (c + d <  W) best = fminf(best, sB[c + d] + dd);
        }
        num += sqrtf(best);
        den += 1.0f;
    }

    // warp shuffle reduction (deterministic)
    #pragma unroll
    for (int off = 16; off > 0; off >>= 1) {
        num += __shfl_down_sync(0xFFFFFFFFu, num, off);
        den += __shfl_down_sync(0xFFFFFFFFu, den, off);
    }
    if (lane == 0) { wNum[wid] = num; wDen[wid] = den; }
    __syncthreads();

    if (wid == 0) {
        float n = (lane < 16) ? wNum[lane] : 0.0f;
        float d = (lane < 16) ? wDen[lane] : 0.0f;
        #pragma unroll
        for (int off = 8; off > 0; off >>= 1) {
            n += __shfl_down_sync(0xFFFFFFFFu, n, off);
            d += __shfl_down_sync(0xFFFFFFFFu, d, off);
        }
        if (lane == 0) {
            d_rowNum[r] = n;
            d_rowDen[r] = d;
            __threadfence();
            unsigned int old = atomicInc(&d_cnt, H - 1);  // wraps -> reset
            isLast = (old == H - 1);
        }
    }
    __syncthreads();

    // last block folds the 512 row partials
    if (isLast) {
        float n = d_rowNum[c];
        float d = d_rowDen[c];
        #pragma unroll
        for (int off = 16; off > 0; off >>= 1) {
            n += __shfl_down_sync(0xFFFFFFFFu, n, off);
            d += __shfl_down_sync(0xFFFFFFFFu, d, off);
        }
        if (lane == 0) { wNum[wid] = n; wDen[wid] = d; }
        __syncthreads();
        if (wid == 0) {
            float nn = (lane < 16) ? wNum[lane] : 0.0f;
            float dd = (lane < 16) ? wDen[lane] : 0.0f;
            #pragma unroll
            for (int off = 8; off > 0; off >>= 1) {
                nn += __shfl_down_sync(0xFFFFFFFFu, nn, off);
                dd += __shfl_down_sync(0xFFFFFFFFu, dd, off);
            }
            if (lane == 0) out[0] = nn / dd;
        }
    }
}

extern "C" void kernel_launch(void* const* d_in, const int* in_sizes, int n_in,
                              void* d_out, int out_size) {
    const float* pred = (const float*)d_in[0];
    const float* gt   = (const float*)d_in[1];
    float* out = (float*)d_out;

    dim3 blk(32, 32);
    dim3 grd(W / 32, H / 32);
    k_pack<<<grd, blk>>>(pred, gt);
    k_fused<<<H, W>>>(out);
}

// round 7
// speedup vs baseline: 1.1400x; 1.0025x over previous
#include <cuda_runtime.h>
#include <cuda_bf16.h>
#include <math.h>

#define H 512
#define W 512
#define NWORDS 16              // 512 rows / 32 bits
#define GRID 512               // one block per row; blocks 0..255 also pack

// Scratch (allocation-free rule: __device__ globals)
__device__ unsigned d_packA[NWORDS * W];   // bit j of [q*W+c] = S  at (q*32+j, c)
__device__ unsigned d_packB[NWORDS * W];   // bit j of [q*W+c] = S' at (q*32+j, c)
__device__ float d_rowNum[H];
__device__ float d_rowDen[H];
__device__ unsigned d_cnt;                 // zero-init; atomicInc wraps -> reset
__device__ unsigned d_bar;                 // grid barrier; reset by final block

// ---------------------------------------------------------------------------
// 32x32 bit-matrix transpose within one warp (butterfly, 5 steps).
// ---------------------------------------------------------------------------
__device__ __forceinline__ unsigned bit_transpose32(unsigned x, int lane) {
    #pragma unroll
    for (int i = 0; i < 5; ++i) {
        const int s = 16 >> i;
        const unsigned m = (i == 0) ? 0xFFFF0000u :
                           (i == 1) ? 0xFF00FF00u :
                           (i == 2) ? 0xF0F0F0F0u :
                           (i == 3) ? 0xCCCCCCCCu : 0xAAAAAAAAu;
        unsigned y = __shfl_xor_sync(0xFFFFFFFFu, x, s);
        x = (lane & s) ? ((x & m) | ((y >> s) & ~m))
                       : ((x & ~m) | ((y << s) & m));
    }
    return x;
}

// ---------------------------------------------------------------------------
// Exact vertical squared distance using a 3-word (96-bit) window; cold
// fallback beyond +-32 rows has probability ~6e-7 per pixel.
// ---------------------------------------------------------------------------
__device__ __forceinline__ float vdist2_win(unsigned wc, unsigned wp, unsigned wn,
                                            int q, int bit,
                                            const unsigned* __restrict__ col) {
    // rows <= r: wp at positions 0..31, masked wc at 32..32+bit; offset = (bit+32)-pos
    unsigned long long up =
        (((unsigned long long)(wc & (0xFFFFFFFFu >> (31 - bit)))) << 32) |
        (unsigned long long)wp;
    // rows >= r: wc>>bit at positions 0..31-bit, wn at 32-bit..63-bit; offset = pos
    unsigned long long dn =
        (((unsigned long long)wn) << (32 - bit)) | (unsigned long long)(wc >> bit);

    int du, dd;
    if (up) {
        du = (bit + 32) - (63 - __clzll(up));
    } else {
        du = 1 << 20;
        for (int s = 2; s <= q; ++s) {
            unsigned x = col[(q - s) * W];
            if (x) { du = bit + s * 32 - (31 - __clz(x)); break; }
        }
    }
    if (dn) {
        dd = __ffsll((long long)dn) - 1;
    } else {
        dd = 1 << 20;
        for (int s = 2; q + s < NWORDS; ++s) {
            unsigned x = col[(q + s) * W];
            if (x) { dd = (32 - bit) + (s - 1) * 32 + (__ffs(x) - 1); break; }
        }
    }
    int dm = min(du, dd);
    if (dm >= (1 << 20)) return 1e12f;
    float f = (float)dm;
    return f * f;
}

// ---------------------------------------------------------------------------
// Single persistent kernel. Phase 1 (blocks 0..255): pack one 32x32 tile.
// Grid barrier. Phase 2 (all blocks): per-row EDT + masked sums + fold.
// __launch_bounds__(512, 4): regs <= 32 -> 4 blocks/SM -> all 512 blocks
// co-resident in wave 1 (capacity >= 592), so the barrier cannot deadlock.
// ---------------------------------------------------------------------------
__global__ void __launch_bounds__(512, 4) k_all(const float* __restrict__ pred,
                                                const float* __restrict__ gt,
                                                float* __restrict__ out) {
    __shared__ unsigned rawA[34], rawB[34];   // tile row words + halo rows
    __shared__ unsigned surA[32], surB[32];   // surface row words
    __shared__ float sA[W], sB[W];
    __shared__ float wNum[16], wDen[16];
    __shared__ bool  isLast;

    const int tid = threadIdx.x;
    const int lane = tid & 31;
    const int w = tid >> 5;                   // warp 0..15

    // ===================== Phase 1: pack (blocks 0..255) =====================
    if (blockIdx.x < 256) {
        const int tile = blockIdx.x;
        const int c0 = (tile & 15) * 32;
        const int r0 = (tile >> 4) * 32;

        unsigned wAreg[2], wBreg[2];
        unsigned hA[2], hB[2];                // bit0 = left halo, bit1 = right halo

        #pragma unroll
        for (int k = 0; k < 2; ++k) {
            const int rr = 2 * w + k;
            const int r = r0 + rr;
            const float* prow = pred + r * W;
            const float* grow = gt + r * W;
            unsigned a = __ballot_sync(0xFFFFFFFFu, prow[c0 + lane] != 0.0f);
            unsigned b = __ballot_sync(0xFFFFFFFFu, grow[c0 + lane] != 0.0f);
            if (lane == 0) { rawA[rr + 1] = a; rawB[rr + 1] = b; }
            wAreg[k] = a; wBreg[k] = b;

            const int hc = (lane == 0) ? (c0 - 1) : (c0 + 32);
            const bool valid = (lane < 2) && (hc >= 0) && (hc < W);
            bool pa = valid && (prow[hc] != 0.0f);
            bool ga = valid && (grow[hc] != 0.0f);
            hA[k] = __ballot_sync(0xFFFFFFFFu, pa) & 3u;
            hB[k] = __ballot_sync(0xFFFFFFFFu, ga) & 3u;
        }
        if (w == 0) {
            bool a = (r0 > 0) && (pred[(r0 - 1) * W + c0 + lane] != 0.0f);
            bool b = (r0 > 0) && (gt[(r0 - 1) * W + c0 + lane] != 0.0f);
            unsigned ha = __ballot_sync(0xFFFFFFFFu, a);
            unsigned hb = __ballot_sync(0xFFFFFFFFu, b);
            if (lane == 0) { rawA[0] = ha; rawB[0] = hb; }
        } else if (w == 1) {
            bool a = (r0 + 32 < H) && (pred[(r0 + 32) * W + c0 + lane] != 0.0f);
            bool b = (r0 + 32 < H) && (gt[(r0 + 32) * W + c0 + lane] != 0.0f);
            unsigned ha = __ballot_sync(0xFFFFFFFFu, a);
            unsigned hb = __ballot_sync(0xFFFFFFFFu, b);
            if (lane == 0) { rawA[33] = ha; rawB[33] = hb; }
        }
        __syncthreads();

        #pragma unroll
        for (int k = 0; k < 2; ++k) {
            const int rr = 2 * w + k;
            unsigned wA = wAreg[k], wB = wBreg[k];
            unsigned upA = rawA[rr], dnA = rawA[rr + 2];
            unsigned upB = rawB[rr], dnB = rawB[rr + 2];
            unsigned lmA = (wA << 1) | (hA[k] & 1u);
            unsigned rmA = (wA >> 1) | ((hA[k] & 2u) ? 0x80000000u : 0u);
            unsigned lmB = (wB << 1) | (hB[k] & 1u);
            unsigned rmB = (wB >> 1) | ((hB[k] & 2u) ? 0x80000000u : 0u);
            if (lane == 0) {
                surA[rr] = wA & ~(upA & dnA & lmA & rmA);
                surB[rr] = wB & ~(upB & dnB & lmB & rmB);
            }
        }
        __syncthreads();

        if (w == 0) {
            unsigned x = bit_transpose32(surA[lane], lane);
            d_packA[(tile >> 4) * W + c0 + lane] = x;
        } else if (w == 1) {
            unsigned x = bit_transpose32(surB[lane], lane);
            d_packB[(tile >> 4) * W + c0 + lane] = x;
        }
    }

    // ===================== Grid barrier =====================
    __syncthreads();
    if (tid == 0) {
        __threadfence();
        unsigned arrived = atomicAdd(&d_bar, 1u) + 1u;
        if (arrived < GRID) {
            while (atomicAdd(&d_bar, 0u) < GRID) { __nanosleep(64); }
        }
        __threadfence();
    }
    __syncthreads();

    // ===================== Phase 2: per-row EDT + sums =====================
    const int r = blockIdx.x;
    const int c = tid;
    const int q = r >> 5;
    const int bit = r & 31;

    const unsigned pwA = d_packA[q * W + c];
    const unsigned pwB = d_packB[q * W + c];
    const unsigned wpA = (q > 0) ? d_packA[(q - 1) * W + c] : 0u;
    const unsigned wnA = (q < NWORDS - 1) ? d_packA[(q + 1) * W + c] : 0u;
    const unsigned wpB = (q > 0) ? d_packB[(q - 1) * W + c] : 0u;
    const unsigned wnB = (q < NWORDS - 1) ? d_packB[(q + 1) * W + c] : 0u;

    const bool onS  = (pwA >> bit) & 1u;
    const bool onSp = (pwB >> bit) & 1u;

    sA[c] = vdist2_win(pwA, wpA, wnA, q, bit, &d_packA[c]);
    sB[c] = vdist2_win(pwB, wpB, wnB, q, bit, &d_packB[c]);
    __syncthreads();

    float num = 0.0f;
    float den = 0.0f;

    if (onSp) {   // dta sampled on S'
        float best = sA[c];
        #pragma unroll
        for (int d = 1; d <= 3; ++d) {
            float dd = (float)(d * d);
            if (c - d >= 0) best = fminf(best, sA[c - d] + dd);
            if (c + d <  W) best = fminf(best, sA[c + d] + dd);
        }
        for (int d = 4; d < W; ++d) {
            float dd = (float)(d * d);
            if (dd >= best) break;
            if (c - d >= 0) best = fminf(best, sA[c - d] + dd);
            if (c + d <  W) best = fminf(best, sA[c + d] + dd);
        }
        num += sqrtf(best);
        den += 1.0f;
    }
    if (onS) {    // dtb sampled on S
        float best = sB[c];
        #pragma unroll
        for (int d = 1; d <= 3; ++d) {
            float dd = (float)(d * d);
            if (c - d >= 0) best = fminf(best, sB[c - d] + dd);
            if (c + d <  W) best = fminf(best, sB[c + d] + dd);
        }
        for (int d = 4; d < W; ++d) {
            float dd = (float)(d * d);
            if (dd >= best) break;
            if (c - d >= 0) best = fminf(best, sB[c - d] + dd);
            if (c + d <  W) best = fminf(best, sB[c + d] + dd);
        }
        num += sqrtf(best);
        den += 1.0f;
    }

    // warp shuffle reduction (deterministic)
    #pragma unroll
    for (int off = 16; off > 0; off >>= 1) {
        num += __shfl_down_sync(0xFFFFFFFFu, num, off);
        den += __shfl_down_sync(0xFFFFFFFFu, den, off);
    }
    if (lane == 0) { wNum[w] = num; wDen[w] = den; }
    __syncthreads();

    if (w == 0) {
        float n = (lane < 16) ? wNum[lane] : 0.0f;
        float d = (lane < 16) ? wDen[lane] : 0.0f;
        #pragma unroll
        for (int off = 8; off > 0; off >>= 1) {
            n += __shfl_down_sync(0xFFFFFFFFu, n, off);
            d += __shfl_down_sync(0xFFFFFFFFu, d, off);
        }
        if (lane == 0) {
            d_rowNum[r] = n;
            d_rowDen[r] = d;
            __threadfence();
            unsigned old = atomicInc(&d_cnt, H - 1);   // wraps -> self-reset
            isLast = (old == H - 1);
        }
    }
    __syncthreads();

    if (isLast) {
        float n = d_rowNum[c];
        float d = d_rowDen[c];
        #pragma unroll
        for (int off = 16; off > 0; off >>= 1) {
            n += __shfl_down_sync(0xFFFFFFFFu, n, off);
            d += __shfl_down_sync(0xFFFFFFFFu, d, off);
        }
        if (lane == 0) { wNum[w] = n; wDen[w] = d; }
        __syncthreads();
        if (w == 0) {
            float nn = (lane < 16) ? wNum[lane] : 0.0f;
            float dd = (lane < 16) ? wDen[lane] : 0.0f;
            #pragma unroll
            for (int off = 8; off > 0; off >>= 1) {
                nn += __shfl_down_sync(0xFFFFFFFFu, nn, off);
                dd += __shfl_down_sync(0xFFFFFFFFu, dd, off);
            }
            if (lane == 0) {
                out[0] = nn / dd;
                d_bar = 0u;          // reset grid barrier for next replay
            }
        }
    }
}

extern "C" void kernel_launch(void* const* d_in, const int* in_sizes, int n_in,
                              void* d_out, int out_size) {
    const float* pred = (const float*)d_in[0];
    const float* gt   = (const float*)d_in[1];
    float* out = (float*)d_out;

    k_all<<<GRID, 512>>>(pred, gt, out);
}